// round 1
// baseline (speedup 1.0000x reference)
#include <cuda_runtime.h>

// LSTM single step, B=64, H=I=O=2048.
// out[64, 6144] = concat(y, h_new, c_new) along features.
//   gates_g = h_prev @ Wgh + x @ Wgx + bg   (g = f, i, c~, o)
//   c = sig(f)*c_prev + sig(i)*tanh(c~);  h = sig(o)*tanh(c);  y = h_prev@Wy + by

#define BQ 64
#define KD 2048
#define NOUT 6144

typedef unsigned long long u64;

// Scratch (static device globals; no allocation in kernel_launch).
__device__ float2 g_hT[KD * BQ];          // hT_dup[k][r] = (h[r][k], h[r][k])
__device__ float2 g_xT[KD * BQ];          // xT_dup
__device__ float  g_gates[4 * BQ * KD];   // biased pre-activations per gate

__device__ __forceinline__ u64 ffma2(u64 a, u64 b, u64 c) {
    u64 d;
    asm("fma.rn.f32x2 %0, %1, %2, %3;" : "=l"(d) : "l"(a), "l"(b), "l"(c));
    return d;
}
__device__ __forceinline__ float2 u2f2(u64 v) {
    float2 f;
    asm("mov.b64 {%0, %1}, %2;" : "=f"(f.x), "=f"(f.y) : "l"(v));
    return f;
}

// ---------------------------------------------------------------------------
// Prologue: transpose + duplicate h_prev and x into float2(a,a) scratch.
// ---------------------------------------------------------------------------
__global__ void transpose_dup(const float* __restrict__ h,
                              const float* __restrict__ x) {
    int idx = blockIdx.x * 256 + threadIdx.x;   // 2 * 2048 * 64 = 262144 total
    int m = idx >> 17;                          // 0: h, 1: x
    int i = idx & 131071;
    int k = i >> 6, r = i & 63;
    if (m == 0) {
        float v = h[r * KD + k];
        g_hT[i] = make_float2(v, v);
    } else {
        float v = x[r * KD + k];
        g_xT[i] = make_float2(v, v);
    }
}

// ---------------------------------------------------------------------------
// GEMM: grid.x = 160.  Blocks 0..127: gate blocks (gate = bx&3, 64-col tile,
// K = 4096 across (hT,Wgh) then (xT,Wgx)).  Blocks 128..159: y blocks
// (K = 2048, (hT,Wy)), writing out[:, 0:2048] directly with bias.
// Block tile 64x64, 256 threads, 4x4 per-thread tile as packed f32x2 accums.
// ---------------------------------------------------------------------------
__global__ __launch_bounds__(256) void gemm_kernel(
    const float* __restrict__ Wfh, const float* __restrict__ Wfx, const float* __restrict__ bf,
    const float* __restrict__ Wih, const float* __restrict__ Wix, const float* __restrict__ bi,
    const float* __restrict__ Wch, const float* __restrict__ Wcx, const float* __restrict__ bc,
    const float* __restrict__ Woh, const float* __restrict__ Wox, const float* __restrict__ bo,
    const float* __restrict__ Wy,  const float* __restrict__ by,
    float* __restrict__ out)
{
    __shared__ __align__(16) float2 sA[32 * 64];  // A chunk, dup pairs (16 KB)
    __shared__ __align__(16) float  sW[32 * 64];  // W chunk (8 KB)

    const int t  = threadIdx.x;
    const int bx = blockIdx.x;
    const int tx = t & 15;       // col group: cols tx*4 .. tx*4+3
    const int ty = t >> 4;       // row group: rows ty*4 .. ty*4+3

    const float *W0, *W1 = nullptr, *bias;
    float* Cout;
    int ldc, j0, nChunks;

    if (bx < 128) {
        int g = bx & 3;
        j0 = (bx >> 2) * 64;
        if (g == 0)      { W0 = Wfh; W1 = Wfx; bias = bf; }
        else if (g == 1) { W0 = Wih; W1 = Wix; bias = bi; }
        else if (g == 2) { W0 = Wch; W1 = Wcx; bias = bc; }
        else             { W0 = Woh; W1 = Wox; bias = bo; }
        Cout = g_gates + g * BQ * KD;
        ldc = KD;
        nChunks = 128;           // 2 x (2048/32)
    } else {
        j0 = (bx - 128) * 64;
        W0 = Wy; bias = by;
        Cout = out;              // y goes straight to out[:, 0:2048]
        ldc = NOUT;
        nChunks = 64;
    }

    u64 acc[4][2];
#pragma unroll
    for (int i = 0; i < 4; i++) { acc[i][0] = 0ull; acc[i][1] = 0ull; }

    float4 ra[4], rw[2];

    // Prefetch chunk 0 (always pair 0 == hT, k0 = 0).
    {
        const float4* Ag = (const float4*)g_hT;
#pragma unroll
        for (int i = 0; i < 4; i++) ra[i] = Ag[t + i * 256];
#pragma unroll
        for (int i = 0; i < 2; i++) {
            int q = t + i * 256;
            rw[i] = *(const float4*)(W0 + (q >> 4) * KD + j0 + (q & 15) * 4);
        }
    }

    for (int cc = 0; cc < nChunks; cc++) {
        __syncthreads();
        // Stage current chunk (both layouts are linear copies -> float4 STS).
#pragma unroll
        for (int i = 0; i < 4; i++) ((float4*)sA)[t + i * 256] = ra[i];
#pragma unroll
        for (int i = 0; i < 2; i++) ((float4*)sW)[t + i * 256] = rw[i];

        // Prefetch next chunk into registers (overlaps with compute below).
        if (cc + 1 < nChunks) {
            int nc = cc + 1;
            const float2* ATb = (nc & 64) ? g_xT : g_hT;
            const float*  Wp  = (nc & 64) ? W1 : W0;
            int k0 = (nc & 63) * 32;
            const float4* Ag = (const float4*)(ATb + k0 * 64);
#pragma unroll
            for (int i = 0; i < 4; i++) ra[i] = Ag[t + i * 256];
#pragma unroll
            for (int i = 0; i < 2; i++) {
                int q = t + i * 256;
                rw[i] = *(const float4*)(Wp + (k0 + (q >> 4)) * KD + j0 + (q & 15) * 4);
            }
        }
        __syncthreads();

        const ulonglong2* sA2 = (const ulonglong2*)sA;  // 2 dup-pairs / load
        const ulonglong2* sW2 = (const ulonglong2*)sW;  // (w0,w1),(w2,w3)
#pragma unroll
        for (int k = 0; k < 32; k++) {
            ulonglong2 v0 = sA2[k * 32 + ty * 2];       // rows ty*4+0, +1
            ulonglong2 v1 = sA2[k * 32 + ty * 2 + 1];   // rows ty*4+2, +3
            ulonglong2 wv = sW2[k * 16 + tx];           // cols tx*4 .. +3
            acc[0][0] = ffma2(v0.x, wv.x, acc[0][0]);
            acc[0][1] = ffma2(v0.x, wv.y, acc[0][1]);
            acc[1][0] = ffma2(v0.y, wv.x, acc[1][0]);
            acc[1][1] = ffma2(v0.y, wv.y, acc[1][1]);
            acc[2][0] = ffma2(v1.x, wv.x, acc[2][0]);
            acc[2][1] = ffma2(v1.x, wv.y, acc[2][1]);
            acc[3][0] = ffma2(v1.y, wv.x, acc[3][0]);
            acc[3][1] = ffma2(v1.y, wv.y, acc[3][1]);
        }
    }

    // Epilogue: add bias, write 4 rows x 4 cols.
    float4 bv = *(const float4*)(bias + j0 + tx * 4);
#pragma unroll
    for (int i = 0; i < 4; i++) {
        float2 p0 = u2f2(acc[i][0]);
        float2 p1 = u2f2(acc[i][1]);
        float4 v = make_float4(p0.x + bv.x, p0.y + bv.y, p1.x + bv.z, p1.y + bv.w);
        *(float4*)(Cout + (ty * 4 + i) * ldc + j0 + tx * 4) = v;
    }
}

// ---------------------------------------------------------------------------
// Elementwise fusion: gates -> (h, c), written to out[:, 2048:6144].
// ---------------------------------------------------------------------------
__global__ void fuse_kernel(const float* __restrict__ c_prev,
                            float* __restrict__ out) {
    int idx = blockIdx.x * 256 + threadIdx.x;   // 64 * 2048
    int r = idx >> 11, j = idx & 2047;
    float gf = g_gates[0 * BQ * KD + idx];
    float gi = g_gates[1 * BQ * KD + idx];
    float gc = g_gates[2 * BQ * KD + idx];
    float go = g_gates[3 * BQ * KD + idx];
    float f  = 1.f / (1.f + expf(-gf));
    float ii = 1.f / (1.f + expf(-gi));
    float ct = tanhf(gc);
    float o  = 1.f / (1.f + expf(-go));
    float c  = f * c_prev[idx] + ii * ct;
    float h  = o * tanhf(c);
    out[r * NOUT + 2048 + j] = h;
    out[r * NOUT + 4096 + j] = c;
}

// ---------------------------------------------------------------------------
extern "C" void kernel_launch(void* const* d_in, const int* in_sizes, int n_in,
                              void* d_out, int out_size) {
    const float* x      = (const float*)d_in[0];
    const float* h_prev = (const float*)d_in[1];
    const float* c_prev = (const float*)d_in[2];
    const float* Wfh = (const float*)d_in[3];
    const float* Wfx = (const float*)d_in[4];
    const float* bf  = (const float*)d_in[5];
    const float* Wih = (const float*)d_in[6];
    const float* Wix = (const float*)d_in[7];
    const float* bi  = (const float*)d_in[8];
    const float* Woh = (const float*)d_in[9];
    const float* Wox = (const float*)d_in[10];
    const float* bo  = (const float*)d_in[11];
    const float* Wch = (const float*)d_in[12];
    const float* Wcx = (const float*)d_in[13];
    const float* bc  = (const float*)d_in[14];
    const float* Wy  = (const float*)d_in[15];
    const float* by  = (const float*)d_in[16];
    float* out = (float*)d_out;

    transpose_dup<<<1024, 256>>>(h_prev, x);
    gemm_kernel<<<160, 256>>>(Wfh, Wfx, bf, Wih, Wix, bi,
                              Wch, Wcx, bc, Woh, Wox, bo,
                              Wy, by, out);
    fuse_kernel<<<512, 256>>>(c_prev, out);
}

// round 3
// speedup vs baseline: 2.5126x; 2.5126x over previous
#include <cuda_runtime.h>
#include <cuda_bf16.h>
#include <cstdint>

// LSTM single step, B=64, H=I=O=2048.
// out[64,6144] = concat(y, h_new, c_new).
// GEMMs via mma.sync bf16 (base sm_103 ISA), fp32 emulated by hi/lo bf16 split:
//   A = Ah + Al, B = Bh + Bl;  C ~= Ah*Bh + Ah*Bl + Al*Bh  (Al*Bl ~ 2^-16, dropped)

#define KD 2048
#define NOUT 6144

__device__ __nv_bfloat16 g_A[128 * 4096];   // rows 0-63: hi(concat(h,x)), 64-127: lo
__device__ float g_gates[4 * 64 * KD];

#define SWZ128(o) ((o) ^ (((o) >> 3) & 0x70))

__device__ __forceinline__ uint32_t smem_u32(const void* p) {
    uint32_t a;
    asm("{ .reg .u64 t; cvta.to.shared.u64 t, %1; cvt.u32.u64 %0, t; }"
        : "=r"(a) : "l"(p));
    return a;
}

#define LDSM4(r, addr)                                                       \
    asm volatile("ldmatrix.sync.aligned.m8n8.x4.shared.b16 {%0,%1,%2,%3}, [%4];" \
                 : "=r"((r)[0]), "=r"((r)[1]), "=r"((r)[2]), "=r"((r)[3])    \
                 : "r"(addr))
#define LDSM4T(r, addr)                                                      \
    asm volatile("ldmatrix.sync.aligned.m8n8.x4.trans.shared.b16 {%0,%1,%2,%3}, [%4];" \
                 : "=r"((r)[0]), "=r"((r)[1]), "=r"((r)[2]), "=r"((r)[3])    \
                 : "r"(addr))
#define MMA16816(d, a, b0, b1)                                               \
    asm volatile("mma.sync.aligned.m16n8k16.row.col.f32.bf16.bf16.f32 "      \
                 "{%0,%1,%2,%3}, {%4,%5,%6,%7}, {%8,%9}, {%0,%1,%2,%3};"     \
                 : "+f"((d)[0]), "+f"((d)[1]), "+f"((d)[2]), "+f"((d)[3])    \
                 : "r"((a)[0]), "r"((a)[1]), "r"((a)[2]), "r"((a)[3]),       \
                   "r"(b0), "r"(b1))
#define CP_ASYNC16(saddr, gptr)                                              \
    asm volatile("cp.async.cg.shared.global [%0], [%1], 16;" :: "r"(saddr), "l"(gptr))
#define CP_COMMIT() asm volatile("cp.async.commit_group;" ::: "memory")
#define CP_WAIT1()  asm volatile("cp.async.wait_group 1;" ::: "memory")

// ---------------------------------------------------------------------------
// Prologue: split concat(h, x) into bf16 hi/lo, packed along rows of g_A.
// ---------------------------------------------------------------------------
__global__ void make_A(const float* __restrict__ h, const float* __restrict__ x) {
    int idx = blockIdx.x * 256 + threadIdx.x;   // 64 * 4096
    int r = idx >> 12, k = idx & 4095;
    float a = (k < 2048) ? h[r * 2048 + k] : x[r * 2048 + (k - 2048)];
    __nv_bfloat16 ah = __float2bfloat16(a);
    __nv_bfloat16 al = __float2bfloat16(a - __bfloat162float(ah));
    g_A[r * 4096 + k] = ah;
    g_A[(r + 64) * 4096 + k] = al;
}

// ---------------------------------------------------------------------------
// GEMM. 160 CTAs: 0..127 gate tiles (g=bx>>5, 64 cols, K=4096);
// 128..159 y tiles (K=2048). CTA tile C = 64(M) x 64(N).
// 8 warps: mi = w&3 (16 rows), ni = w>>2 (32 cols).
// SMEM per stage (stride 32768): A bf16 128x64 (16KB), Bh 64x64 (8KB), Bl (8KB).
// ---------------------------------------------------------------------------
__global__ void __launch_bounds__(256, 2) gemm_hmma(
    const float* __restrict__ Wfh, const float* __restrict__ Wfx, const float* __restrict__ bf_,
    const float* __restrict__ Wih, const float* __restrict__ Wix, const float* __restrict__ bi_,
    const float* __restrict__ Wch, const float* __restrict__ Wcx, const float* __restrict__ bc_,
    const float* __restrict__ Woh, const float* __restrict__ Wox, const float* __restrict__ bo_,
    const float* __restrict__ Wy,  const float* __restrict__ by_,
    float* __restrict__ out)
{
    extern __shared__ char smem[];
    const uint32_t su = smem_u32(smem);
    const int t = threadIdx.x, bx = blockIdx.x;
    const int lane = t & 31, wid = t >> 5;
    const int mi = wid & 3, ni = wid >> 2;

    const float* WH[4] = {Wfh, Wih, Wch, Woh};
    const float* WX[4] = {Wfx, Wix, Wcx, Wox};
    const float* BB[4] = {bf_, bi_, bc_, bo_};

    const float *W0, *W1, *bias;
    float* Cout;
    int ldc, jj, nIter;
    if (bx < 128) {
        int g = bx >> 5;
        jj = (bx & 31) * 64;
        W0 = WH[g]; W1 = WX[g]; bias = BB[g];
        Cout = g_gates + g * 64 * KD + jj;
        ldc = KD; nIter = 64;
    } else {
        jj = (bx - 128) * 64;
        W0 = Wy; W1 = Wy; bias = by_;
        Cout = out + jj;
        ldc = NOUT; nIter = 32;
    }

    // Per-thread staging roles.
    const int arow = t >> 1, aseg = t & 1;            // A: 128 rows x 2 segs
    const int brow = t >> 2, bseg = t & 3;            // B: 64 k-rows x 4 segs

    float acc[4][4];
#pragma unroll
    for (int j = 0; j < 4; j++)
#pragma unroll
        for (int q = 0; q < 4; q++) acc[j][q] = 0.f;

    // --- prologue: cp.async A(0) into stage 0; LDG B(0) into regs ---
    {
        const __nv_bfloat16* asrc = g_A + (size_t)arow * 4096 + aseg * 32;
        const uint32_t abase = su + SWZ128(arow * 128 + aseg * 64);
        // note: SWZ within 16B-aligned chunks: apply per 16B piece
        CP_ASYNC16(su + 0 + SWZ128(arow * 128 + aseg * 64 +  0), (const char*)asrc +  0);
        CP_ASYNC16(su + 0 + SWZ128(arow * 128 + aseg * 64 + 16), (const char*)asrc + 16);
        CP_ASYNC16(su + 0 + SWZ128(arow * 128 + aseg * 64 + 32), (const char*)asrc + 32);
        CP_ASYNC16(su + 0 + SWZ128(arow * 128 + aseg * 64 + 48), (const char*)asrc + 48);
        (void)abase;
        CP_COMMIT();
    }
    float4 rb[4];
    {
        const float* src = W0 + (size_t)brow * 2048 + jj + bseg * 16;
        rb[0] = *(const float4*)(src + 0);
        rb[1] = *(const float4*)(src + 4);
        rb[2] = *(const float4*)(src + 8);
        rb[3] = *(const float4*)(src + 12);
    }

    for (int it = 0; it < nIter; ++it) {
        const int s = it & 1;
        const uint32_t aOff  = (uint32_t)s * 32768u;
        const uint32_t bhOff = aOff + 16384u;
        const uint32_t blOff = bhOff + 8192u;

        // issue cp.async A(it+1) into the other stage
        if (it + 1 < nIter) {
            const int k0n = (it + 1) * 64;
            const uint32_t ao = (uint32_t)((it + 1) & 1) * 32768u;
            const __nv_bfloat16* asrc = g_A + (size_t)arow * 4096 + k0n + aseg * 32;
            const uint32_t rbase = arow * 128 + aseg * 64;
            CP_ASYNC16(su + ao + SWZ128(rbase +  0), (const char*)asrc +  0);
            CP_ASYNC16(su + ao + SWZ128(rbase + 16), (const char*)asrc + 16);
            CP_ASYNC16(su + ao + SWZ128(rbase + 32), (const char*)asrc + 32);
            CP_ASYNC16(su + ao + SWZ128(rbase + 48), (const char*)asrc + 48);
        }
        CP_COMMIT();

        // convert + STS B(it) from regs into stage s
        {
            float f[16] = {rb[0].x, rb[0].y, rb[0].z, rb[0].w,
                           rb[1].x, rb[1].y, rb[1].z, rb[1].w,
                           rb[2].x, rb[2].y, rb[2].z, rb[2].w,
                           rb[3].x, rb[3].y, rb[3].z, rb[3].w};
            uint32_t hi[8], lo[8];
#pragma unroll
            for (int p = 0; p < 8; p++) {
                __nv_bfloat162 hh = __floats2bfloat162_rn(f[2*p], f[2*p+1]);
                float2 hf = __bfloat1622float2(hh);
                __nv_bfloat162 ll = __floats2bfloat162_rn(f[2*p] - hf.x, f[2*p+1] - hf.y);
                hi[p] = *reinterpret_cast<uint32_t*>(&hh);
                lo[p] = *reinterpret_cast<uint32_t*>(&ll);
            }
            const uint32_t rbse = brow * 128 + bseg * 32;
            const uint32_t o0 = SWZ128(rbse), o1 = SWZ128(rbse + 16);
            *(uint4*)(smem + bhOff + o0) = make_uint4(hi[0], hi[1], hi[2], hi[3]);
            *(uint4*)(smem + bhOff + o1) = make_uint4(hi[4], hi[5], hi[6], hi[7]);
            *(uint4*)(smem + blOff + o0) = make_uint4(lo[0], lo[1], lo[2], lo[3]);
            *(uint4*)(smem + blOff + o1) = make_uint4(lo[4], lo[5], lo[6], lo[7]);
        }

        CP_WAIT1();
        __syncthreads();

        // prefetch B(it+1) fp32 into regs (latency hidden by compute below)
        if (it + 1 < nIter) {
            const int k0n = (it + 1) * 64;
            const float* wsrc = (k0n < 2048) ? W0 : W1;
            const float* src = wsrc + (size_t)((k0n & 2047) + brow) * 2048 + jj + bseg * 16;
            rb[0] = *(const float4*)(src + 0);
            rb[1] = *(const float4*)(src + 4);
            rb[2] = *(const float4*)(src + 8);
            rb[3] = *(const float4*)(src + 12);
        }

        // compute stage s
        {
            const uint32_t aBase  = su + aOff;
            const uint32_t bhBase = su + bhOff;
            const uint32_t blBase = su + blOff;
            const int lr = lane & 15, lc = lane >> 4;
#pragma unroll
            for (int ks = 0; ks < 4; ks++) {
                uint32_t ah[4], al[4];
                const uint32_t ac = ks * 32 + lc * 16;
                LDSM4(ah, aBase + SWZ128((mi * 16 + lr) * 128 + ac));
                LDSM4(al, aBase + SWZ128((mi * 16 + lr + 64) * 128 + ac));
                const uint32_t brw = (ks * 16 + lr) * 128;
#pragma unroll
                for (int nc = 0; nc < 2; nc++) {
                    const uint32_t bo = SWZ128(brw + ni * 64 + nc * 32 + lc * 16);
                    uint32_t bh[4], bl[4];
                    LDSM4T(bh, bhBase + bo);
                    LDSM4T(bl, blBase + bo);
                    MMA16816(acc[nc*2+0], ah, bh[0], bh[1]);
                    MMA16816(acc[nc*2+1], ah, bh[2], bh[3]);
                    MMA16816(acc[nc*2+0], ah, bl[0], bl[1]);
                    MMA16816(acc[nc*2+1], ah, bl[2], bl[3]);
                    MMA16816(acc[nc*2+0], al, bh[0], bh[1]);
                    MMA16816(acc[nc*2+1], al, bh[2], bh[3]);
                }
            }
        }
        __syncthreads();
    }

    // Epilogue: each lane owns (m, m+8) x 4 n8-tiles, 2 cols each.
    {
        const int m0 = mi * 16 + (lane >> 2);
        const int c2 = (lane & 3) * 2;
#pragma unroll
        for (int j = 0; j < 4; j++) {
            const int n = ni * 32 + j * 8 + c2;
            const float b0 = bias[jj + n], b1 = bias[jj + n + 1];
            *(float2*)(Cout + (size_t)m0 * ldc + n) =
                make_float2(acc[j][0] + b0, acc[j][1] + b1);
            *(float2*)(Cout + (size_t)(m0 + 8) * ldc + n) =
                make_float2(acc[j][2] + b0, acc[j][3] + b1);
        }
    }
}

// ---------------------------------------------------------------------------
// Elementwise fusion: gates -> (h, c) into out[:, 2048:6144].
// ---------------------------------------------------------------------------
__global__ void fuse_kernel(const float* __restrict__ c_prev, float* __restrict__ out) {
    int idx = blockIdx.x * 256 + threadIdx.x;   // 64 * 2048
    int r = idx >> 11, j = idx & 2047;
    float gf = g_gates[0 * 64 * KD + idx];
    float gi = g_gates[1 * 64 * KD + idx];
    float gc = g_gates[2 * 64 * KD + idx];
    float go = g_gates[3 * 64 * KD + idx];
    float f  = 1.f / (1.f + expf(-gf));
    float ii = 1.f / (1.f + expf(-gi));
    float ct = tanhf(gc);
    float o  = 1.f / (1.f + expf(-go));
    float c  = f * c_prev[idx] + ii * ct;
    float h  = o * tanhf(c);
    out[r * NOUT + 2048 + j] = h;
    out[r * NOUT + 4096 + j] = c;
}

// ---------------------------------------------------------------------------
extern "C" void kernel_launch(void* const* d_in, const int* in_sizes, int n_in,
                              void* d_out, int out_size) {
    const float* x      = (const float*)d_in[0];
    const float* h_prev = (const float*)d_in[1];
    const float* c_prev = (const float*)d_in[2];
    const float* Wfh = (const float*)d_in[3];
    const float* Wfx = (const float*)d_in[4];
    const float* bf  = (const float*)d_in[5];
    const float* Wih = (const float*)d_in[6];
    const float* Wix = (const float*)d_in[7];
    const float* bi  = (const float*)d_in[8];
    const float* Woh = (const float*)d_in[9];
    const float* Wox = (const float*)d_in[10];
    const float* bo  = (const float*)d_in[11];
    const float* Wch = (const float*)d_in[12];
    const float* Wcx = (const float*)d_in[13];
    const float* bc  = (const float*)d_in[14];
    const float* Wy  = (const float*)d_in[15];
    const float* by  = (const float*)d_in[16];
    float* out = (float*)d_out;

    static int smem_set = 0;
    if (!smem_set) {
        cudaFuncSetAttribute(gemm_hmma, cudaFuncAttributeMaxDynamicSharedMemorySize, 65536);
        smem_set = 1;
    }

    make_A<<<1024, 256>>>(h_prev, x);
    gemm_hmma<<<160, 256, 65536>>>(Wfh, Wfx, bf, Wih, Wix, bi,
                                   Wch, Wcx, bc, Woh, Wox, bo,
                                   Wy, by, out);
    fuse_kernel<<<512, 256>>>(c_prev, out);
}

// round 4
// speedup vs baseline: 3.3408x; 1.3296x over previous
#include <cuda_runtime.h>
#include <cuda_fp16.h>
#include <cstdint>

// LSTM single step, B=64, H=I=O=2048.  out[64,6144] = concat(y, h_new, c_new).
// GEMMs via mma.sync fp16 (base sm_103 ISA).
// Numerics: A (activations) in fp16 (1 limb, err ~2^-11); B (weights) in fp16
// 2 limbs: B = Bh + Bl*2^-11 (Bl stored scaled by 2^11; separate accumulator,
// recombined at epilogue).  Expected rel_err ~1e-4.

#define KD 2048
#define NOUT 6144
#define LO_SCALE 2048.0f
#define INV_LO (1.0f / 2048.0f)

__device__ __half g_A[64 * 4096];        // concat(h, x) in fp16
__device__ float g_gates[4 * 64 * KD];

#define SWZ128(o) ((o) ^ (((o) >> 3) & 0x70))

__device__ __forceinline__ uint32_t smem_u32(const void* p) {
    uint32_t a;
    asm("{ .reg .u64 t; cvta.to.shared.u64 t, %1; cvt.u32.u64 %0, t; }"
        : "=r"(a) : "l"(p));
    return a;
}

#define LDSM4(r, addr)                                                       \
    asm volatile("ldmatrix.sync.aligned.m8n8.x4.shared.b16 {%0,%1,%2,%3}, [%4];" \
                 : "=r"((r)[0]), "=r"((r)[1]), "=r"((r)[2]), "=r"((r)[3])    \
                 : "r"(addr))
#define LDSM4T(r, addr)                                                      \
    asm volatile("ldmatrix.sync.aligned.m8n8.x4.trans.shared.b16 {%0,%1,%2,%3}, [%4];" \
                 : "=r"((r)[0]), "=r"((r)[1]), "=r"((r)[2]), "=r"((r)[3])    \
                 : "r"(addr))
#define MMA16816(d, a, b0, b1)                                               \
    asm volatile("mma.sync.aligned.m16n8k16.row.col.f32.f16.f16.f32 "        \
                 "{%0,%1,%2,%3}, {%4,%5,%6,%7}, {%8,%9}, {%0,%1,%2,%3};"     \
                 : "+f"((d)[0]), "+f"((d)[1]), "+f"((d)[2]), "+f"((d)[3])    \
                 : "r"((a)[0]), "r"((a)[1]), "r"((a)[2]), "r"((a)[3]),       \
                   "r"(b0), "r"(b1))
#define CP_ASYNC16(saddr, gptr)                                              \
    asm volatile("cp.async.cg.shared.global [%0], [%1], 16;" :: "r"(saddr), "l"(gptr))
#define CP_COMMIT() asm volatile("cp.async.commit_group;" ::: "memory")
#define CP_WAIT1()  asm volatile("cp.async.wait_group 1;" ::: "memory")

// SMEM layout (relative to 1KB-aligned base):
//   A stages  (3): s*8192              (64 rows x 128B, fp16)
//   Bh stages (2): 24576 + s*16384     (64 k-rows x 128B, fp16)
//   Bl stages (2): 24576 + s*16384 + 8192
#define A_OFF(s)  ((uint32_t)(s) * 8192u)
#define BH_OFF(s) (24576u + (uint32_t)(s) * 16384u)
#define BL_OFF(s) (BH_OFF(s) + 8192u)
#define SMEM_BYTES (57344 + 1024)

// ---------------------------------------------------------------------------
// Prologue: concat(h, x) -> fp16.
// ---------------------------------------------------------------------------
__global__ void make_A(const float* __restrict__ h, const float* __restrict__ x) {
    int idx = blockIdx.x * 256 + threadIdx.x;   // 64 * 4096
    int r = idx >> 12, k = idx & 4095;
    float a = (k < 2048) ? h[r * 2048 + k] : x[r * 2048 + (k - 2048)];
    g_A[idx] = __float2half_rn(a);
}

// ---------------------------------------------------------------------------
// GEMM: 144 CTAs, all doing exactly 64 K-chunks.
//  bx in [0,128): gate tile g=bx>>5, cols jj=(bx&31)*64, K=4096 (h then x).
//  bx in [128,144): y pair p=bx-128: two tiles jjA=p*128, jjB=p*128+64,
//                   each K=2048 (h only), 32 chunks each.
// CTA tile 64(M) x 64(N); 8 warps: mi=w&3 (16 rows), ni=w>>2 (32 cols).
// ---------------------------------------------------------------------------
__global__ void __launch_bounds__(256, 1) gemm_hmma(
    const float* __restrict__ Wfh, const float* __restrict__ Wfx, const float* __restrict__ bf_,
    const float* __restrict__ Wih, const float* __restrict__ Wix, const float* __restrict__ bi_,
    const float* __restrict__ Wch, const float* __restrict__ Wcx, const float* __restrict__ bc_,
    const float* __restrict__ Woh, const float* __restrict__ Wox, const float* __restrict__ bo_,
    const float* __restrict__ Wy,  const float* __restrict__ by_,
    float* __restrict__ out)
{
    extern __shared__ char smem_raw[];
    uint32_t su0 = smem_u32(smem_raw);
    const uint32_t su = (su0 + 1023u) & ~1023u;
    char* sm = smem_raw + (su - su0);

    const int t = threadIdx.x, bx = blockIdx.x;
    const int lane = t & 31, wid = t >> 5;
    const int mi = wid & 3, ni = wid >> 2;
    const int lr = lane & 15, lc = lane >> 4;

    const float* WH[4] = {Wfh, Wih, Wch, Woh};
    const float* WX[4] = {Wfx, Wix, Wcx, Wox};
    const float* BB[4] = {bf_, bi_, bc_, bo_};

    const bool isY = (bx >= 128);
    const float *W0, *W1, *bias;
    float *CoutA, *CoutB;
    int jjA, jjB, ldc;
    if (!isY) {
        int g = bx >> 5;
        int jj = (bx & 31) * 64;
        W0 = WH[g]; W1 = WX[g]; bias = BB[g];
        jjA = jjB = jj;
        CoutA = CoutB = g_gates + g * 64 * KD + jj;
        ldc = KD;
    } else {
        int p = bx - 128;
        jjA = p * 128; jjB = p * 128 + 64;
        W0 = Wy; W1 = Wy; bias = by_;
        CoutA = out + jjA; CoutB = out + jjB;
        ldc = NOUT;
    }

    // Staging roles.
    const int au0 = t * 2, au1 = t * 2 + 1;     // A: 512 16B units
    const int brow = t >> 2, bseg = t & 3;      // B: 64 k-rows x 4 segs

    float acc_h[4][4], acc_l[4][4];
#pragma unroll
    for (int j = 0; j < 4; j++)
#pragma unroll
        for (int q = 0; q < 4; q++) { acc_h[j][q] = 0.f; acc_l[j][q] = 0.f; }

    // --- A issue helper (chunk c -> stage s) ---
    auto issueA = [&](int c, int s) {
        const int aK = (isY ? (c & 31) : c) * 64;
#pragma unroll
        for (int ui = 0; ui < 2; ui++) {
            const int u = (ui == 0) ? au0 : au1;
            const int row = u >> 3, cs = u & 7;
            const uint32_t saddr = su + A_OFF(s) + SWZ128(row * 128 + cs * 16);
            const __half* gsrc = g_A + (size_t)row * 4096 + aK + cs * 8;
            CP_ASYNC16(saddr, gsrc);
        }
    };
    auto ldgB = [&](int c, float4* rb) {
        const float* Wc = (c < 32) ? W0 : W1;
        const int col = (c < 32) ? jjA : jjB;
        const float* src =
            Wc + (size_t)((c & 31) * 64 + brow) * 2048 + col + bseg * 16;
        rb[0] = *(const float4*)(src + 0);
        rb[1] = *(const float4*)(src + 4);
        rb[2] = *(const float4*)(src + 8);
        rb[3] = *(const float4*)(src + 12);
    };

    // Prologue: A(0) -> stage 0; B(0) -> regs.
    issueA(0, 0);
    CP_COMMIT();
    float4 rb[4];
    ldgB(0, rb);

    for (int c = 0; c < 64; ++c) {
        const int sa = c % 3, sb = c & 1;

        // Convert + STS B(c) (hi, lo*2^11) into stage sb.
        {
            float f[16] = {rb[0].x, rb[0].y, rb[0].z, rb[0].w,
                           rb[1].x, rb[1].y, rb[1].z, rb[1].w,
                           rb[2].x, rb[2].y, rb[2].z, rb[2].w,
                           rb[3].x, rb[3].y, rb[3].z, rb[3].w};
            uint32_t hi[8], lo[8];
#pragma unroll
            for (int p = 0; p < 8; p++) {
                __half h0 = __float2half_rn(f[2*p]);
                __half h1 = __float2half_rn(f[2*p+1]);
                float r0 = (f[2*p]   - __half2float(h0)) * LO_SCALE;
                float r1 = (f[2*p+1] - __half2float(h1)) * LO_SCALE;
                __half2 hh = __halves2half2(h0, h1);
                __half2 ll = __floats2half2_rn(r0, r1);
                hi[p] = *reinterpret_cast<uint32_t*>(&hh);
                lo[p] = *reinterpret_cast<uint32_t*>(&ll);
            }
            const uint32_t rbse = brow * 128 + bseg * 32;
            const uint32_t o0 = SWZ128(rbse), o1 = SWZ128(rbse + 16);
            *(uint4*)(sm + BH_OFF(sb) + o0) = make_uint4(hi[0], hi[1], hi[2], hi[3]);
            *(uint4*)(sm + BH_OFF(sb) + o1) = make_uint4(hi[4], hi[5], hi[6], hi[7]);
            *(uint4*)(sm + BL_OFF(sb) + o0) = make_uint4(lo[0], lo[1], lo[2], lo[3]);
            *(uint4*)(sm + BL_OFF(sb) + o1) = make_uint4(lo[4], lo[5], lo[6], lo[7]);
        }

        // Issue A(c+1); keep group accounting uniform.
        if (c + 1 < 64) issueA(c + 1, (c + 1) % 3);
        CP_COMMIT();
        CP_WAIT1();           // A(c) resident
        __syncthreads();

        // Prefetch B(c+1) into regs (hidden under compute).
        if (c + 1 < 64) ldgB(c + 1, rb);

        // Compute chunk c.
        {
            const uint32_t aBase  = su + A_OFF(sa);
            const uint32_t bhBase = su + BH_OFF(sb);
            const uint32_t blBase = su + BL_OFF(sb);
#pragma unroll
            for (int ks = 0; ks < 4; ks++) {
                uint32_t a[4];
                LDSM4(a, aBase + SWZ128((mi * 16 + lr) * 128 + ks * 32 + lc * 16));
                const uint32_t brw = (ks * 16 + lr) * 128;
#pragma unroll
                for (int nc = 0; nc < 2; nc++) {
                    const uint32_t bo = SWZ128(brw + ni * 64 + nc * 32 + lc * 16);
                    uint32_t bh[4], bl[4];
                    LDSM4T(bh, bhBase + bo);
                    LDSM4T(bl, blBase + bo);
                    MMA16816(acc_h[nc*2+0], a, bh[0], bh[1]);
                    MMA16816(acc_h[nc*2+1], a, bh[2], bh[3]);
                    MMA16816(acc_l[nc*2+0], a, bl[0], bl[1]);
                    MMA16816(acc_l[nc*2+1], a, bl[2], bl[3]);
                }
            }
        }

        // Epilogue(s).
        const bool epi = (c == 63) || (isY && c == 31);
        if (epi) {
            float* Cout = (c == 31) ? CoutA : CoutB;
            const int jj = (c == 31) ? jjA : jjB;
            const int m0 = mi * 16 + (lane >> 2);
            const int c2 = (lane & 3) * 2;
#pragma unroll
            for (int j = 0; j < 4; j++) {
                const int n = ni * 32 + j * 8 + c2;
                const float b0 = bias[jj + n], b1 = bias[jj + n + 1];
                *(float2*)(Cout + (size_t)m0 * ldc + n) = make_float2(
                    acc_h[j][0] + acc_l[j][0] * INV_LO + b0,
                    acc_h[j][1] + acc_l[j][1] * INV_LO + b1);
                *(float2*)(Cout + (size_t)(m0 + 8) * ldc + n) = make_float2(
                    acc_h[j][2] + acc_l[j][2] * INV_LO + b0,
                    acc_h[j][3] + acc_l[j][3] * INV_LO + b1);
            }
            if (c == 31) {
#pragma unroll
                for (int j = 0; j < 4; j++)
#pragma unroll
                    for (int q = 0; q < 4; q++) { acc_h[j][q] = 0.f; acc_l[j][q] = 0.f; }
            }
        }
    }
}

// ---------------------------------------------------------------------------
// Elementwise fusion: gates -> (h, c) into out[:, 2048:6144].
// ---------------------------------------------------------------------------
__global__ void fuse_kernel(const float* __restrict__ c_prev, float* __restrict__ out) {
    int idx = blockIdx.x * 256 + threadIdx.x;   // 64 * 2048
    int r = idx >> 11, j = idx & 2047;
    float gf = g_gates[0 * 64 * KD + idx];
    float gi = g_gates[1 * 64 * KD + idx];
    float gc = g_gates[2 * 64 * KD + idx];
    float go = g_gates[3 * 64 * KD + idx];
    float f  = 1.f / (1.f + expf(-gf));
    float ii = 1.f / (1.f + expf(-gi));
    float ct = tanhf(gc);
    float o  = 1.f / (1.f + expf(-go));
    float c  = f * c_prev[idx] + ii * ct;
    float h  = o * tanhf(c);
    out[r * NOUT + 2048 + j] = h;
    out[r * NOUT + 4096 + j] = c;
}

// ---------------------------------------------------------------------------
extern "C" void kernel_launch(void* const* d_in, const int* in_sizes, int n_in,
                              void* d_out, int out_size) {
    const float* x      = (const float*)d_in[0];
    const float* h_prev = (const float*)d_in[1];
    const float* c_prev = (const float*)d_in[2];
    const float* Wfh = (const float*)d_in[3];
    const float* Wfx = (const float*)d_in[4];
    const float* bf  = (const float*)d_in[5];
    const float* Wih = (const float*)d_in[6];
    const float* Wix = (const float*)d_in[7];
    const float* bi  = (const float*)d_in[8];
    const float* Woh = (const float*)d_in[9];
    const float* Wox = (const float*)d_in[10];
    const float* bo  = (const float*)d_in[11];
    const float* Wch = (const float*)d_in[12];
    const float* Wcx = (const float*)d_in[13];
    const float* bc  = (const float*)d_in[14];
    const float* Wy  = (const float*)d_in[15];
    const float* by  = (const float*)d_in[16];
    float* out = (float*)d_out;

    static int smem_set = 0;
    if (!smem_set) {
        cudaFuncSetAttribute(gemm_hmma, cudaFuncAttributeMaxDynamicSharedMemorySize,
                             SMEM_BYTES);
        smem_set = 1;
    }

    make_A<<<1024, 256>>>(h_prev, x);
    gemm_hmma<<<144, 256, SMEM_BYTES>>>(Wfh, Wfx, bf, Wih, Wix, bi,
                                        Wch, Wcx, bc, Woh, Wox, bo,
                                        Wy, by, out);
    fuse_kernel<<<512, 256>>>(c_prev, out);
}

// round 5
// speedup vs baseline: 3.4849x; 1.0431x over previous
#include <cuda_runtime.h>
#include <cuda_fp16.h>
#include <cstdint>

// LSTM single step, B=64, H=I=O=2048.  out[64,6144] = concat(y, h_new, c_new).
// GEMMs via mma.sync fp16 (base sm_103 ISA), fp32 accumulate.
// Numerics: A fp16 1-limb, B fp16 1-limb -> rel_err ~2.7e-4 (< 1e-3 gate).

#define KD 2048
#define NOUT 6144

__device__ __half g_A[64 * 4096];        // concat(h, x) in fp16
__device__ float g_gates[4 * 64 * KD];

#define SWZ128(o) ((o) ^ (((o) >> 3) & 0x70))

__device__ __forceinline__ uint32_t smem_u32(const void* p) {
    uint32_t a;
    asm("{ .reg .u64 t; cvta.to.shared.u64 t, %1; cvt.u32.u64 %0, t; }"
        : "=r"(a) : "l"(p));
    return a;
}

#define LDSM4(r, addr)                                                       \
    asm volatile("ldmatrix.sync.aligned.m8n8.x4.shared.b16 {%0,%1,%2,%3}, [%4];" \
                 : "=r"((r)[0]), "=r"((r)[1]), "=r"((r)[2]), "=r"((r)[3])    \
                 : "r"(addr))
#define LDSM4T(r, addr)                                                      \
    asm volatile("ldmatrix.sync.aligned.m8n8.x4.trans.shared.b16 {%0,%1,%2,%3}, [%4];" \
                 : "=r"((r)[0]), "=r"((r)[1]), "=r"((r)[2]), "=r"((r)[3])    \
                 : "r"(addr))
#define MMA16816(d, a, b0, b1)                                               \
    asm volatile("mma.sync.aligned.m16n8k16.row.col.f32.f16.f16.f32 "        \
                 "{%0,%1,%2,%3}, {%4,%5,%6,%7}, {%8,%9}, {%0,%1,%2,%3};"     \
                 : "+f"((d)[0]), "+f"((d)[1]), "+f"((d)[2]), "+f"((d)[3])    \
                 : "r"((a)[0]), "r"((a)[1]), "r"((a)[2]), "r"((a)[3]),       \
                   "r"(b0), "r"(b1))
#define CP_ASYNC16(saddr, gptr)                                              \
    asm volatile("cp.async.cg.shared.global [%0], [%1], 16;" :: "r"(saddr), "l"(gptr))
#define CP_COMMIT() asm volatile("cp.async.commit_group;" ::: "memory")
#define CP_WAIT1()  asm volatile("cp.async.wait_group 1;" ::: "memory")

// SMEM (relative to 1KB-aligned base):
//   A stages (3): s*8192            (64 rows x 128B fp16)
//   B stages (2): 24576 + s*8192    (64 k-rows x 128B fp16)
#define A_OFF(s)  ((uint32_t)(s) * 8192u)
#define B_OFF(s)  (24576u + (uint32_t)(s) * 8192u)
#define SMEM_BYTES (40960 + 1024)

// ---------------------------------------------------------------------------
// Prologue: concat(h, x) -> fp16, 8 elems/thread.
// ---------------------------------------------------------------------------
__global__ void make_A(const float* __restrict__ h, const float* __restrict__ x) {
    int u = blockIdx.x * 256 + threadIdx.x;     // 32768 units of 8 elems
    int idx = u * 8;
    int r = idx >> 12, k = idx & 4095;
    const float* src = (k < 2048) ? (h + r * 2048 + k) : (x + r * 2048 + (k - 2048));
    float4 v0 = *(const float4*)(src + 0);
    float4 v1 = *(const float4*)(src + 4);
    __half2 p0 = __floats2half2_rn(v0.x, v0.y);
    __half2 p1 = __floats2half2_rn(v0.z, v0.w);
    __half2 p2 = __floats2half2_rn(v1.x, v1.y);
    __half2 p3 = __floats2half2_rn(v1.z, v1.w);
    *(uint4*)(g_A + idx) = make_uint4(*(uint32_t*)&p0, *(uint32_t*)&p1,
                                      *(uint32_t*)&p2, *(uint32_t*)&p3);
}

// ---------------------------------------------------------------------------
// GEMM: 144 CTAs, all exactly 64 K-chunks.
//  bx in [0,128): gate tile g=bx>>5, cols jj=(bx&31)*64, K=4096 (h then x).
//  bx in [128,144): y pair p=bx-128: tiles jjA=p*128, jjB=p*128+64, K=2048 each.
// CTA tile 64(M) x 64(N); 8 warps: mi=w&3 (16 rows), ni=w>>2 (32 cols).
// ---------------------------------------------------------------------------
__global__ void __launch_bounds__(256, 1) gemm_hmma(
    const float* __restrict__ Wfh, const float* __restrict__ Wfx, const float* __restrict__ bf_,
    const float* __restrict__ Wih, const float* __restrict__ Wix, const float* __restrict__ bi_,
    const float* __restrict__ Wch, const float* __restrict__ Wcx, const float* __restrict__ bc_,
    const float* __restrict__ Woh, const float* __restrict__ Wox, const float* __restrict__ bo_,
    const float* __restrict__ Wy,  const float* __restrict__ by_,
    float* __restrict__ out)
{
    extern __shared__ char smem_raw[];
    uint32_t su0 = smem_u32(smem_raw);
    const uint32_t su = (su0 + 1023u) & ~1023u;
    char* sm = smem_raw + (su - su0);

    const int t = threadIdx.x, bx = blockIdx.x;
    const int lane = t & 31, wid = t >> 5;
    const int mi = wid & 3, ni = wid >> 2;
    const int lr = lane & 15, lc = lane >> 4;

    const float* WH[4] = {Wfh, Wih, Wch, Woh};
    const float* WX[4] = {Wfx, Wix, Wcx, Wox};
    const float* BB[4] = {bf_, bi_, bc_, bo_};

    const bool isY = (bx >= 128);
    const float *W0, *W1, *bias;
    float *CoutA, *CoutB;
    int jjA, jjB, ldc;
    if (!isY) {
        int g = bx >> 5;
        int jj = (bx & 31) * 64;
        W0 = WH[g]; W1 = WX[g]; bias = BB[g];
        jjA = jjB = jj;
        CoutA = CoutB = g_gates + g * 64 * KD + jj;
        ldc = KD;
    } else {
        int p = bx - 128;
        jjA = p * 128; jjB = p * 128 + 64;
        W0 = Wy; W1 = Wy; bias = by_;
        CoutA = out + jjA; CoutB = out + jjB;
        ldc = NOUT;
    }

    // Staging roles.
    const int brow = t >> 2, bseg = t & 3;      // B: 64 k-rows x 4 segs of 16 cols

    float acc[4][4];
#pragma unroll
    for (int j = 0; j < 4; j++)
#pragma unroll
        for (int q = 0; q < 4; q++) acc[j][q] = 0.f;

    auto issueA = [&](int c, int s) {
        const int aK = (isY ? (c & 31) : c) * 64;
#pragma unroll
        for (int ui = 0; ui < 2; ui++) {
            const int u = t * 2 + ui;
            const int row = u >> 3, cs = u & 7;
            const uint32_t saddr = su + A_OFF(s) + SWZ128(row * 128 + cs * 16);
            const __half* gsrc = g_A + (size_t)row * 4096 + aK + cs * 8;
            CP_ASYNC16(saddr, gsrc);
        }
    };
    auto ldgB = [&](int c, float4* rb) {
        const float* Wc = (c < 32) ? W0 : W1;
        const int col = (c < 32) ? jjA : jjB;
        const float* src =
            Wc + (size_t)((c & 31) * 64 + brow) * 2048 + col + bseg * 16;
        rb[0] = *(const float4*)(src + 0);
        rb[1] = *(const float4*)(src + 4);
        rb[2] = *(const float4*)(src + 8);
        rb[3] = *(const float4*)(src + 12);
    };

    issueA(0, 0);
    CP_COMMIT();
    float4 rb[4];
    ldgB(0, rb);

    for (int c = 0; c < 64; ++c) {
        const int sa = c % 3, sb = c & 1;

        // Convert + STS B(c) fp32 -> fp16 into stage sb.
        {
            __half2 p[8];
            p[0] = __floats2half2_rn(rb[0].x, rb[0].y);
            p[1] = __floats2half2_rn(rb[0].z, rb[0].w);
            p[2] = __floats2half2_rn(rb[1].x, rb[1].y);
            p[3] = __floats2half2_rn(rb[1].z, rb[1].w);
            p[4] = __floats2half2_rn(rb[2].x, rb[2].y);
            p[5] = __floats2half2_rn(rb[2].z, rb[2].w);
            p[6] = __floats2half2_rn(rb[3].x, rb[3].y);
            p[7] = __floats2half2_rn(rb[3].z, rb[3].w);
            const uint32_t rbse = brow * 128 + bseg * 32;
            *(uint4*)(sm + B_OFF(sb) + SWZ128(rbse)) =
                make_uint4(*(uint32_t*)&p[0], *(uint32_t*)&p[1],
                           *(uint32_t*)&p[2], *(uint32_t*)&p[3]);
            *(uint4*)(sm + B_OFF(sb) + SWZ128(rbse + 16)) =
                make_uint4(*(uint32_t*)&p[4], *(uint32_t*)&p[5],
                           *(uint32_t*)&p[6], *(uint32_t*)&p[7]);
        }

        if (c + 1 < 64) issueA(c + 1, (c + 1) % 3);
        CP_COMMIT();
        CP_WAIT1();           // A(c) resident
        __syncthreads();

        if (c + 1 < 64) ldgB(c + 1, rb);

        // Compute chunk c: 16 MMAs / warp.
        {
            const uint32_t aBase = su + A_OFF(sa);
            const uint32_t bBase = su + B_OFF(sb);
#pragma unroll
            for (int ks = 0; ks < 4; ks++) {
                uint32_t a[4];
                LDSM4(a, aBase + SWZ128((mi * 16 + lr) * 128 + ks * 32 + lc * 16));
                const uint32_t brw = (ks * 16 + lr) * 128;
#pragma unroll
                for (int nc = 0; nc < 2; nc++) {
                    uint32_t b[4];
                    LDSM4T(b, bBase + SWZ128(brw + ni * 64 + nc * 32 + lc * 16));
                    MMA16816(acc[nc*2+0], a, b[0], b[1]);
                    MMA16816(acc[nc*2+1], a, b[2], b[3]);
                }
            }
        }

        const bool epi = (c == 63) || (isY && c == 31);
        if (epi) {
            float* Cout = (c == 31) ? CoutA : CoutB;
            const int jj = (c == 31) ? jjA : jjB;
            const int m0 = mi * 16 + (lane >> 2);
            const int c2 = (lane & 3) * 2;
#pragma unroll
            for (int j = 0; j < 4; j++) {
                const int n = ni * 32 + j * 8 + c2;
                const float b0 = bias[jj + n], b1 = bias[jj + n + 1];
                *(float2*)(Cout + (size_t)m0 * ldc + n) =
                    make_float2(acc[j][0] + b0, acc[j][1] + b1);
                *(float2*)(Cout + (size_t)(m0 + 8) * ldc + n) =
                    make_float2(acc[j][2] + b0, acc[j][3] + b1);
            }
            if (c == 31) {
#pragma unroll
                for (int j = 0; j < 4; j++)
#pragma unroll
                    for (int q = 0; q < 4; q++) acc[j][q] = 0.f;
            }
        }
    }
}

// ---------------------------------------------------------------------------
// Elementwise fusion: gates -> (h, c) into out[:, 2048:6144].
// ---------------------------------------------------------------------------
__global__ void fuse_kernel(const float* __restrict__ c_prev, float* __restrict__ out) {
    int idx = blockIdx.x * 256 + threadIdx.x;   // 64 * 2048
    int r = idx >> 11, j = idx & 2047;
    float gf = g_gates[0 * 64 * KD + idx];
    float gi = g_gates[1 * 64 * KD + idx];
    float gc = g_gates[2 * 64 * KD + idx];
    float go = g_gates[3 * 64 * KD + idx];
    float f  = 1.f / (1.f + expf(-gf));
    float ii = 1.f / (1.f + expf(-gi));
    float ct = tanhf(gc);
    float o  = 1.f / (1.f + expf(-go));
    float c  = f * c_prev[idx] + ii * ct;
    float h  = o * tanhf(c);
    out[r * NOUT + 2048 + j] = h;
    out[r * NOUT + 4096 + j] = c;
}

// ---------------------------------------------------------------------------
extern "C" void kernel_launch(void* const* d_in, const int* in_sizes, int n_in,
                              void* d_out, int out_size) {
    const float* x      = (const float*)d_in[0];
    const float* h_prev = (const float*)d_in[1];
    const float* c_prev = (const float*)d_in[2];
    const float* Wfh = (const float*)d_in[3];
    const float* Wfx = (const float*)d_in[4];
    const float* bf  = (const float*)d_in[5];
    const float* Wih = (const float*)d_in[6];
    const float* Wix = (const float*)d_in[7];
    const float* bi  = (const float*)d_in[8];
    const float* Woh = (const float*)d_in[9];
    const float* Wox = (const float*)d_in[10];
    const float* bo  = (const float*)d_in[11];
    const float* Wch = (const float*)d_in[12];
    const float* Wcx = (const float*)d_in[13];
    const float* bc  = (const float*)d_in[14];
    const float* Wy  = (const float*)d_in[15];
    const float* by  = (const float*)d_in[16];
    float* out = (float*)d_out;

    static int smem_set = 0;
    if (!smem_set) {
        cudaFuncSetAttribute(gemm_hmma, cudaFuncAttributeMaxDynamicSharedMemorySize,
                             SMEM_BYTES);
        smem_set = 1;
    }

    make_A<<<128, 256>>>(h_prev, x);
    gemm_hmma<<<144, 256, SMEM_BYTES>>>(Wfh, Wfx, bf, Wih, Wix, bi,
                                        Wch, Wcx, bc, Woh, Wox, bo,
                                        Wy, by, out);
    fuse_kernel<<<512, 256>>>(c_prev, out);
}

// round 6
// speedup vs baseline: 4.9772x; 1.4282x over previous
#include <cuda_runtime.h>
#include <cuda_fp16.h>
#include <cstdint>

// LSTM single step, B=64, H=I=O=2048.  out[64,6144] = concat(y, h_new, c_new).
// mma.sync fp16 (base sm_103 ISA), fp32 accumulate; A/B single-limb fp16.
// Split-K: each gate tile split at the h/x boundary -> 256 gate CTAs + 32 y
// CTAs = 288 CTAs x 32 K-chunks, 2 CTAs/SM for latency overlap.

#define KD 2048
#define NOUT 6144

__device__ __half g_A[64 * 4096];            // concat(h, x) fp16
__device__ float g_part[2][4 * 64 * KD];     // split-K gate partials

#define SWZ128(o) ((o) ^ (((o) >> 3) & 0x70))

__device__ __forceinline__ uint32_t smem_u32(const void* p) {
    uint32_t a;
    asm("{ .reg .u64 t; cvta.to.shared.u64 t, %1; cvt.u32.u64 %0, t; }"
        : "=r"(a) : "l"(p));
    return a;
}

#define LDSM4(r, addr)                                                       \
    asm volatile("ldmatrix.sync.aligned.m8n8.x4.shared.b16 {%0,%1,%2,%3}, [%4];" \
                 : "=r"((r)[0]), "=r"((r)[1]), "=r"((r)[2]), "=r"((r)[3])    \
                 : "r"(addr))
#define LDSM4T(r, addr)                                                      \
    asm volatile("ldmatrix.sync.aligned.m8n8.x4.trans.shared.b16 {%0,%1,%2,%3}, [%4];" \
                 : "=r"((r)[0]), "=r"((r)[1]), "=r"((r)[2]), "=r"((r)[3])    \
                 : "r"(addr))
#define MMA16816(d, a, b0, b1)                                               \
    asm volatile("mma.sync.aligned.m16n8k16.row.col.f32.f16.f16.f32 "        \
                 "{%0,%1,%2,%3}, {%4,%5,%6,%7}, {%8,%9}, {%0,%1,%2,%3};"     \
                 : "+f"((d)[0]), "+f"((d)[1]), "+f"((d)[2]), "+f"((d)[3])    \
                 : "r"((a)[0]), "r"((a)[1]), "r"((a)[2]), "r"((a)[3]),       \
                   "r"(b0), "r"(b1))
#define CP_ASYNC16(saddr, gptr)                                              \
    asm volatile("cp.async.cg.shared.global [%0], [%1], 16;" :: "r"(saddr), "l"(gptr))
#define CP_COMMIT() asm volatile("cp.async.commit_group;" ::: "memory")
#define CP_WAIT1()  asm volatile("cp.async.wait_group 1;" ::: "memory")

// SMEM (relative to 1KB-aligned base):
//   A stages (3): s*8192           (64 rows x 128B fp16)
//   B stages (2): 24576 + s*8192
#define A_OFF(s)  ((uint32_t)(s) * 8192u)
#define B_OFF(s)  (24576u + (uint32_t)(s) * 8192u)
#define SMEM_BYTES (40960 + 1024)

// ---------------------------------------------------------------------------
__global__ void make_A(const float* __restrict__ h, const float* __restrict__ x) {
    int u = blockIdx.x * 256 + threadIdx.x;     // 32768 units of 8 elems
    int idx = u * 8;
    int r = idx >> 12, k = idx & 4095;
    const float* src = (k < 2048) ? (h + r * 2048 + k) : (x + r * 2048 + (k - 2048));
    float4 v0 = *(const float4*)(src + 0);
    float4 v1 = *(const float4*)(src + 4);
    __half2 p0 = __floats2half2_rn(v0.x, v0.y);
    __half2 p1 = __floats2half2_rn(v0.z, v0.w);
    __half2 p2 = __floats2half2_rn(v1.x, v1.y);
    __half2 p3 = __floats2half2_rn(v1.z, v1.w);
    *(uint4*)(g_A + idx) = make_uint4(*(uint32_t*)&p0, *(uint32_t*)&p1,
                                      *(uint32_t*)&p2, *(uint32_t*)&p3);
}

// ---------------------------------------------------------------------------
// GEMM: 288 CTAs x 32 K-chunks (k64 each).
//  bx in [0,256): tile=bx>>1 (g=tile>>5, jj=(tile&31)*64), kk=bx&1.
//      W = kk ? Wgx : Wgh; A cols (kk*2048 ..). Partial -> g_part[kk][g].
//  bx in [256,288): y tile jj=(bx-256)*64, W=Wy, A = h half, bias, -> out.
// CTA tile 64(M) x 64(N); 8 warps: mi=w&3 (16 rows), ni=w>>2 (32 cols).
// ---------------------------------------------------------------------------
__global__ void __launch_bounds__(256, 2) gemm_hmma(
    const float* __restrict__ Wfh, const float* __restrict__ Wfx,
    const float* __restrict__ Wih, const float* __restrict__ Wix,
    const float* __restrict__ Wch, const float* __restrict__ Wcx,
    const float* __restrict__ Woh, const float* __restrict__ Wox,
    const float* __restrict__ Wy,  const float* __restrict__ by_,
    float* __restrict__ out)
{
    extern __shared__ char smem_raw[];
    uint32_t su0 = smem_u32(smem_raw);
    const uint32_t su = (su0 + 1023u) & ~1023u;
    char* sm = smem_raw + (su - su0);

    const int t = threadIdx.x, bx = blockIdx.x;
    const int lane = t & 31, wid = t >> 5;
    const int mi = wid & 3, ni = wid >> 2;
    const int lr = lane & 15, lc = lane >> 4;

    const float* WH[4] = {Wfh, Wih, Wch, Woh};
    const float* WX[4] = {Wfx, Wix, Wcx, Wox};

    const bool isY = (bx >= 256);
    const float *W, *bias = by_;
    float* Cout;
    int jj, ldc, aCol0;
    if (!isY) {
        const int tile = bx >> 1, kk = bx & 1;
        const int g = tile >> 5;
        jj = (tile & 31) * 64;
        W = kk ? WX[g] : WH[g];
        aCol0 = kk * 2048;
        Cout = g_part[kk] + g * 64 * KD + jj;
        ldc = KD;
    } else {
        jj = (bx - 256) * 64;
        W = Wy;
        aCol0 = 0;
        Cout = out + jj;
        ldc = NOUT;
    }

    const int brow = t >> 2, bseg = t & 3;      // B: 64 k-rows x 4 segs

    float acc[4][4];
#pragma unroll
    for (int j = 0; j < 4; j++)
#pragma unroll
        for (int q = 0; q < 4; q++) acc[j][q] = 0.f;

    auto issueA = [&](int c, int s) {
        const int aK = aCol0 + c * 64;
#pragma unroll
        for (int ui = 0; ui < 2; ui++) {
            const int u = t * 2 + ui;
            const int row = u >> 3, cs = u & 7;
            const uint32_t saddr = su + A_OFF(s) + SWZ128(row * 128 + cs * 16);
            const __half* gsrc = g_A + (size_t)row * 4096 + aK + cs * 8;
            CP_ASYNC16(saddr, gsrc);
        }
    };
    auto ldgB = [&](int c, float4* rb) {
        const float* src = W + (size_t)(c * 64 + brow) * 2048 + jj + bseg * 16;
        rb[0] = *(const float4*)(src + 0);
        rb[1] = *(const float4*)(src + 4);
        rb[2] = *(const float4*)(src + 8);
        rb[3] = *(const float4*)(src + 12);
    };

    issueA(0, 0);
    CP_COMMIT();
    float4 rb[4];
    ldgB(0, rb);

    for (int c = 0; c < 32; ++c) {
        const int sa = c % 3, sb = c & 1;

        // Convert + STS B(c) fp32 -> fp16.
        {
            __half2 p[8];
            p[0] = __floats2half2_rn(rb[0].x, rb[0].y);
            p[1] = __floats2half2_rn(rb[0].z, rb[0].w);
            p[2] = __floats2half2_rn(rb[1].x, rb[1].y);
            p[3] = __floats2half2_rn(rb[1].z, rb[1].w);
            p[4] = __floats2half2_rn(rb[2].x, rb[2].y);
            p[5] = __floats2half2_rn(rb[2].z, rb[2].w);
            p[6] = __floats2half2_rn(rb[3].x, rb[3].y);
            p[7] = __floats2half2_rn(rb[3].z, rb[3].w);
            const uint32_t rbse = brow * 128 + bseg * 32;
            *(uint4*)(sm + B_OFF(sb) + SWZ128(rbse)) =
                make_uint4(*(uint32_t*)&p[0], *(uint32_t*)&p[1],
                           *(uint32_t*)&p[2], *(uint32_t*)&p[3]);
            *(uint4*)(sm + B_OFF(sb) + SWZ128(rbse + 16)) =
                make_uint4(*(uint32_t*)&p[4], *(uint32_t*)&p[5],
                           *(uint32_t*)&p[6], *(uint32_t*)&p[7]);
        }

        if (c + 1 < 32) issueA(c + 1, (c + 1) % 3);
        CP_COMMIT();
        CP_WAIT1();           // A(c) resident
        __syncthreads();

        if (c + 1 < 32) ldgB(c + 1, rb);

        // Compute chunk c: 16 MMAs / warp.
        {
            const uint32_t aBase = su + A_OFF(sa);
            const uint32_t bBase = su + B_OFF(sb);
#pragma unroll
            for (int ks = 0; ks < 4; ks++) {
                uint32_t a[4];
                LDSM4(a, aBase + SWZ128((mi * 16 + lr) * 128 + ks * 32 + lc * 16));
                const uint32_t brw = (ks * 16 + lr) * 128;
#pragma unroll
                for (int nc = 0; nc < 2; nc++) {
                    uint32_t b[4];
                    LDSM4T(b, bBase + SWZ128(brw + ni * 64 + nc * 32 + lc * 16));
                    MMA16816(acc[nc*2+0], a, b[0], b[1]);
                    MMA16816(acc[nc*2+1], a, b[2], b[3]);
                }
            }
        }
    }

    // Epilogue.
    {
        const int m0 = mi * 16 + (lane >> 2);
        const int c2 = (lane & 3) * 2;
#pragma unroll
        for (int j = 0; j < 4; j++) {
            const int n = ni * 32 + j * 8 + c2;
            float b0 = 0.f, b1 = 0.f;
            if (isY) { b0 = bias[jj + n]; b1 = bias[jj + n + 1]; }
            *(float2*)(Cout + (size_t)m0 * ldc + n) =
                make_float2(acc[j][0] + b0, acc[j][1] + b1);
            *(float2*)(Cout + (size_t)(m0 + 8) * ldc + n) =
                make_float2(acc[j][2] + b0, acc[j][3] + b1);
        }
    }
}

// ---------------------------------------------------------------------------
// Fuse: sum split-K partials + bias, LSTM pointwise, write h,c.
// ---------------------------------------------------------------------------
__global__ void fuse_kernel(const float* __restrict__ c_prev,
                            const float* __restrict__ bf_, const float* __restrict__ bi_,
                            const float* __restrict__ bc_, const float* __restrict__ bo_,
                            float* __restrict__ out) {
    int idx = blockIdx.x * 256 + threadIdx.x;   // 64 * 2048
    int r = idx >> 11, j = idx & 2047;
    float gf = g_part[0][0 * 64 * KD + idx] + g_part[1][0 * 64 * KD + idx] + bf_[j];
    float gi = g_part[0][1 * 64 * KD + idx] + g_part[1][1 * 64 * KD + idx] + bi_[j];
    float gc = g_part[0][2 * 64 * KD + idx] + g_part[1][2 * 64 * KD + idx] + bc_[j];
    float go = g_part[0][3 * 64 * KD + idx] + g_part[1][3 * 64 * KD + idx] + bo_[j];
    float f  = 1.f / (1.f + expf(-gf));
    float ii = 1.f / (1.f + expf(-gi));
    float ct = tanhf(gc);
    float o  = 1.f / (1.f + expf(-go));
    float c  = f * c_prev[idx] + ii * ct;
    float h  = o * tanhf(c);
    out[r * NOUT + 2048 + j] = h;
    out[r * NOUT + 4096 + j] = c;
}

// ---------------------------------------------------------------------------
extern "C" void kernel_launch(void* const* d_in, const int* in_sizes, int n_in,
                              void* d_out, int out_size) {
    const float* x      = (const float*)d_in[0];
    const float* h_prev = (const float*)d_in[1];
    const float* c_prev = (const float*)d_in[2];
    const float* Wfh = (const float*)d_in[3];
    const float* Wfx = (const float*)d_in[4];
    const float* bf  = (const float*)d_in[5];
    const float* Wih = (const float*)d_in[6];
    const float* Wix = (const float*)d_in[7];
    const float* bi  = (const float*)d_in[8];
    const float* Woh = (const float*)d_in[9];
    const float* Wox = (const float*)d_in[10];
    const float* bo  = (const float*)d_in[11];
    const float* Wch = (const float*)d_in[12];
    const float* Wcx = (const float*)d_in[13];
    const float* bc  = (const float*)d_in[14];
    const float* Wy  = (const float*)d_in[15];
    const float* by  = (const float*)d_in[16];
    float* out = (float*)d_out;

    static int smem_set = 0;
    if (!smem_set) {
        cudaFuncSetAttribute(gemm_hmma, cudaFuncAttributeMaxDynamicSharedMemorySize,
                             SMEM_BYTES);
        smem_set = 1;
    }

    make_A<<<128, 256>>>(h_prev, x);
    gemm_hmma<<<288, 256, SMEM_BYTES>>>(Wfh, Wfx, Wih, Wix, Wch, Wcx, Woh, Wox,
                                        Wy, by, out);
    fuse_kernel<<<512, 256>>>(c_prev, bf, bi, bc, bo, out);
}

// round 7
// speedup vs baseline: 5.0362x; 1.0118x over previous
#include <cuda_runtime.h>
#include <cuda_fp16.h>
#include <cstdint>

// LSTM single step, B=64, H=I=O=2048.  out[64,6144] = concat(y, h_new, c_new).
// mma.sync fp16 with FP16 accumulate (double-rate path), dumped to fp32 master
// registers every K=32 to bound accumulation error (~5e-4 total).
// Split-K: 256 gate CTAs (h/x halves) + 32 y CTAs = 288 x 32 chunks, 2 CTA/SM.

#define KD 2048
#define NOUT 6144

__device__ __half g_A[64 * 4096];            // concat(h, x) fp16
__device__ float g_part[2][4 * 64 * KD];     // split-K gate partials

#define SWZ128(o) ((o) ^ (((o) >> 3) & 0x70))

__device__ __forceinline__ uint32_t smem_u32(const void* p) {
    uint32_t a;
    asm("{ .reg .u64 t; cvta.to.shared.u64 t, %1; cvt.u32.u64 %0, t; }"
        : "=r"(a) : "l"(p));
    return a;
}

#define LDSM4(r, addr)                                                       \
    asm volatile("ldmatrix.sync.aligned.m8n8.x4.shared.b16 {%0,%1,%2,%3}, [%4];" \
                 : "=r"((r)[0]), "=r"((r)[1]), "=r"((r)[2]), "=r"((r)[3])    \
                 : "r"(addr))
#define LDSM4T(r, addr)                                                      \
    asm volatile("ldmatrix.sync.aligned.m8n8.x4.trans.shared.b16 {%0,%1,%2,%3}, [%4];" \
                 : "=r"((r)[0]), "=r"((r)[1]), "=r"((r)[2]), "=r"((r)[3])    \
                 : "r"(addr))
// fp16-accumulate MMA: D,C are 2 x .f16x2 regs.
#define MMA16816H(d, a, b0, b1)                                              \
    asm volatile("mma.sync.aligned.m16n8k16.row.col.f16.f16.f16.f16 "        \
                 "{%0,%1}, {%2,%3,%4,%5}, {%6,%7}, {%0,%1};"                 \
                 : "+r"((d)[0]), "+r"((d)[1])                                \
                 : "r"((a)[0]), "r"((a)[1]), "r"((a)[2]), "r"((a)[3]),       \
                   "r"(b0), "r"(b1))
#define CP_ASYNC16(saddr, gptr)                                              \
    asm volatile("cp.async.cg.shared.global [%0], [%1], 16;" :: "r"(saddr), "l"(gptr))
#define CP_COMMIT() asm volatile("cp.async.commit_group;" ::: "memory")
#define CP_WAIT1()  asm volatile("cp.async.wait_group 1;" ::: "memory")

// SMEM (relative to 1KB-aligned base):
//   A stages (3): s*8192           (64 rows x 128B fp16)
//   B stages (2): 24576 + s*8192
#define A_OFF(s)  ((uint32_t)(s) * 8192u)
#define B_OFF(s)  (24576u + (uint32_t)(s) * 8192u)
#define SMEM_BYTES (40960 + 1024)

// ---------------------------------------------------------------------------
// Prologue: concat(h, x) -> fp16.  131072 threads x 2 elems (latency-bound).
// ---------------------------------------------------------------------------
__global__ void make_A(const float* __restrict__ h, const float* __restrict__ x) {
    int u = blockIdx.x * 256 + threadIdx.x;     // 131072 units of 2 elems
    int idx = u * 2;
    int r = idx >> 12, k = idx & 4095;
    const float* src = (k < 2048) ? (h + r * 2048 + k) : (x + r * 2048 + (k - 2048));
    float2 v = *(const float2*)src;
    __half2 p = __floats2half2_rn(v.x, v.y);
    *(uint32_t*)(g_A + idx) = *(uint32_t*)&p;
}

// ---------------------------------------------------------------------------
// GEMM: 288 CTAs x 32 K-chunks (k64 each).
//  bx in [0,256): tile=bx>>1 (g=tile>>5, jj=(tile&31)*64), kk=bx&1.
//      W = kk ? Wgx : Wgh; A cols (kk*2048 ..). Partial -> g_part[kk][g].
//  bx in [256,288): y tile jj=(bx-256)*64, W=Wy, A = h half, bias, -> out.
// CTA tile 64(M) x 64(N); 8 warps: mi=w&3 (16 rows), ni=w>>2 (32 cols).
// ---------------------------------------------------------------------------
__global__ void __launch_bounds__(256, 2) gemm_hmma(
    const float* __restrict__ Wfh, const float* __restrict__ Wfx,
    const float* __restrict__ Wih, const float* __restrict__ Wix,
    const float* __restrict__ Wch, const float* __restrict__ Wcx,
    const float* __restrict__ Woh, const float* __restrict__ Wox,
    const float* __restrict__ Wy,  const float* __restrict__ by_,
    float* __restrict__ out)
{
    extern __shared__ char smem_raw[];
    uint32_t su0 = smem_u32(smem_raw);
    const uint32_t su = (su0 + 1023u) & ~1023u;
    char* sm = smem_raw + (su - su0);

    const int t = threadIdx.x, bx = blockIdx.x;
    const int lane = t & 31, wid = t >> 5;
    const int mi = wid & 3, ni = wid >> 2;
    const int lr = lane & 15, lc = lane >> 4;

    const float* WH[4] = {Wfh, Wih, Wch, Woh};
    const float* WX[4] = {Wfx, Wix, Wcx, Wox};

    const bool isY = (bx >= 256);
    const float *W, *bias = by_;
    float* Cout;
    int jj, ldc, aCol0;
    if (!isY) {
        const int tile = bx >> 1, kk = bx & 1;
        const int g = tile >> 5;
        jj = (tile & 31) * 64;
        W = kk ? WX[g] : WH[g];
        aCol0 = kk * 2048;
        Cout = g_part[kk] + g * 64 * KD + jj;
        ldc = KD;
    } else {
        jj = (bx - 256) * 64;
        W = Wy;
        aCol0 = 0;
        Cout = out + jj;
        ldc = NOUT;
    }

    const int brow = t >> 2, bseg = t & 3;      // B: 64 k-rows x 4 segs

    float master[4][4];
    uint32_t acch[4][2];
#pragma unroll
    for (int j = 0; j < 4; j++) {
#pragma unroll
        for (int q = 0; q < 4; q++) master[j][q] = 0.f;
        acch[j][0] = 0u; acch[j][1] = 0u;
    }

    auto issueA = [&](int c, int s) {
        const int aK = aCol0 + c * 64;
#pragma unroll
        for (int ui = 0; ui < 2; ui++) {
            const int u = t * 2 + ui;
            const int row = u >> 3, cs = u & 7;
            const uint32_t saddr = su + A_OFF(s) + SWZ128(row * 128 + cs * 16);
            const __half* gsrc = g_A + (size_t)row * 4096 + aK + cs * 8;
            CP_ASYNC16(saddr, gsrc);
        }
    };
    auto ldgB = [&](int c, float4* rb) {
        const float* src = W + (size_t)(c * 64 + brow) * 2048 + jj + bseg * 16;
        rb[0] = *(const float4*)(src + 0);
        rb[1] = *(const float4*)(src + 4);
        rb[2] = *(const float4*)(src + 8);
        rb[3] = *(const float4*)(src + 12);
    };

    issueA(0, 0);
    CP_COMMIT();
    float4 rb[4];
    ldgB(0, rb);

    for (int c = 0; c < 32; ++c) {
        const int sa = c % 3, sb = c & 1;

        // Convert + STS B(c) fp32 -> fp16.
        {
            __half2 p[8];
            p[0] = __floats2half2_rn(rb[0].x, rb[0].y);
            p[1] = __floats2half2_rn(rb[0].z, rb[0].w);
            p[2] = __floats2half2_rn(rb[1].x, rb[1].y);
            p[3] = __floats2half2_rn(rb[1].z, rb[1].w);
            p[4] = __floats2half2_rn(rb[2].x, rb[2].y);
            p[5] = __floats2half2_rn(rb[2].z, rb[2].w);
            p[6] = __floats2half2_rn(rb[3].x, rb[3].y);
            p[7] = __floats2half2_rn(rb[3].z, rb[3].w);
            const uint32_t rbse = brow * 128 + bseg * 32;
            *(uint4*)(sm + B_OFF(sb) + SWZ128(rbse)) =
                make_uint4(*(uint32_t*)&p[0], *(uint32_t*)&p[1],
                           *(uint32_t*)&p[2], *(uint32_t*)&p[3]);
            *(uint4*)(sm + B_OFF(sb) + SWZ128(rbse + 16)) =
                make_uint4(*(uint32_t*)&p[4], *(uint32_t*)&p[5],
                           *(uint32_t*)&p[6], *(uint32_t*)&p[7]);
        }

        if (c + 1 < 32) issueA(c + 1, (c + 1) % 3);
        CP_COMMIT();
        CP_WAIT1();           // A(c) resident
        __syncthreads();

        if (c + 1 < 32) ldgB(c + 1, rb);

        // Compute chunk c: 16 fp16-accum MMAs / warp; dump to fp32 every 2 k16.
        {
            const uint32_t aBase = su + A_OFF(sa);
            const uint32_t bBase = su + B_OFF(sb);
#pragma unroll
            for (int ks = 0; ks < 4; ks++) {
                uint32_t a[4];
                LDSM4(a, aBase + SWZ128((mi * 16 + lr) * 128 + ks * 32 + lc * 16));
                const uint32_t brw = (ks * 16 + lr) * 128;
#pragma unroll
                for (int nc = 0; nc < 2; nc++) {
                    uint32_t b[4];
                    LDSM4T(b, bBase + SWZ128(brw + ni * 64 + nc * 32 + lc * 16));
                    MMA16816H(acch[nc*2+0], a, b[0], b[1]);
                    MMA16816H(acch[nc*2+1], a, b[2], b[3]);
                }
                if (ks & 1) {   // dump K=32 segment into fp32 master, re-zero
#pragma unroll
                    for (int g2 = 0; g2 < 4; g2++) {
                        float2 lo = __half22float2(*(__half2*)&acch[g2][0]);
                        float2 hi = __half22float2(*(__half2*)&acch[g2][1]);
                        master[g2][0] += lo.x; master[g2][1] += lo.y;
                        master[g2][2] += hi.x; master[g2][3] += hi.y;
                        acch[g2][0] = 0u; acch[g2][1] = 0u;
                    }
                }
            }
        }
    }

    // Epilogue.
    {
        const int m0 = mi * 16 + (lane >> 2);
        const int c2 = (lane & 3) * 2;
#pragma unroll
        for (int j = 0; j < 4; j++) {
            const int n = ni * 32 + j * 8 + c2;
            float b0 = 0.f, b1 = 0.f;
            if (isY) { b0 = bias[jj + n]; b1 = bias[jj + n + 1]; }
            *(float2*)(Cout + (size_t)m0 * ldc + n) =
                make_float2(master[j][0] + b0, master[j][1] + b1);
            *(float2*)(Cout + (size_t)(m0 + 8) * ldc + n) =
                make_float2(master[j][2] + b0, master[j][3] + b1);
        }
    }
}

// ---------------------------------------------------------------------------
// Fuse: sum split-K partials + bias, LSTM pointwise, write h,c.
// ---------------------------------------------------------------------------
__global__ void fuse_kernel(const float* __restrict__ c_prev,
                            const float* __restrict__ bf_, const float* __restrict__ bi_,
                            const float* __restrict__ bc_, const float* __restrict__ bo_,
                            float* __restrict__ out) {
    int idx = blockIdx.x * 256 + threadIdx.x;   // 64 * 2048
    int r = idx >> 11, j = idx & 2047;
    float gf = g_part[0][0 * 64 * KD + idx] + g_part[1][0 * 64 * KD + idx] + bf_[j];
    float gi = g_part[0][1 * 64 * KD + idx] + g_part[1][1 * 64 * KD + idx] + bi_[j];
    float gc = g_part[0][2 * 64 * KD + idx] + g_part[1][2 * 64 * KD + idx] + bc_[j];
    float go = g_part[0][3 * 64 * KD + idx] + g_part[1][3 * 64 * KD + idx] + bo_[j];
    float f  = 1.f / (1.f + expf(-gf));
    float ii = 1.f / (1.f + expf(-gi));
    float ct = tanhf(gc);
    float o  = 1.f / (1.f + expf(-go));
    float c  = f * c_prev[idx] + ii * ct;
    float h  = o * tanhf(c);
    out[r * NOUT + 2048 + j] = h;
    out[r * NOUT + 4096 + j] = c;
}

// ---------------------------------------------------------------------------
extern "C" void kernel_launch(void* const* d_in, const int* in_sizes, int n_in,
                              void* d_out, int out_size) {
    const float* x      = (const float*)d_in[0];
    const float* h_prev = (const float*)d_in[1];
    const float* c_prev = (const float*)d_in[2];
    const float* Wfh = (const float*)d_in[3];
    const float* Wfx = (const float*)d_in[4];
    const float* bf  = (const float*)d_in[5];
    const float* Wih = (const float*)d_in[6];
    const float* Wix = (const float*)d_in[7];
    const float* bi  = (const float*)d_in[8];
    const float* Woh = (const float*)d_in[9];
    const float* Wox = (const float*)d_in[10];
    const float* bo  = (const float*)d_in[11];
    const float* Wch = (const float*)d_in[12];
    const float* Wcx = (const float*)d_in[13];
    const float* bc  = (const float*)d_in[14];
    const float* Wy  = (const float*)d_in[15];
    const float* by  = (const float*)d_in[16];
    float* out = (float*)d_out;

    static int smem_set = 0;
    if (!smem_set) {
        cudaFuncSetAttribute(gemm_hmma, cudaFuncAttributeMaxDynamicSharedMemorySize,
                             SMEM_BYTES);
        smem_set = 1;
    }

    make_A<<<512, 256>>>(h_prev, x);
    gemm_hmma<<<288, 256, SMEM_BYTES>>>(Wfh, Wfx, Wih, Wix, Wch, Wcx, Woh, Wox,
                                        Wy, by, out);
    fuse_kernel<<<512, 256>>>(c_prev, bf, bi, bc, bo, out);
}